// round 3
// baseline (speedup 1.0000x reference)
#include <cuda_runtime.h>
#include <math.h>

#define B_   512
#define L_   20
#define NS_  16
#define EPS_ 32
#define H_   128
#define V_   100000
#define NN_  (B_*NS_)   // 8192 nodes

// ---------------- device scratch (no runtime allocation allowed) ----------------
__device__ float g_x[NN_*H_];
__device__ float g_m[NN_*H_];
__device__ float g_agg[NN_*H_];
__device__ float g_gt[H_*H_];
__device__ float g_gi[NN_*3*H_];
__device__ float g_gh[NN_*3*H_];
__device__ float g_hidden[B_*L_*H_];
__device__ float g_av[B_*H_];

// packed fp32x2 FMA (full-rate FFMA2 on sm_103a; plain 3-reg FFMA is half rate)
#define FMA2(acc, a, b) asm("fma.rn.f32x2 %0, %1, %2, %0;" : "+l"(acc) : "l"(a), "l"(b))

// =================================================================================
// Generic C[M,N] = A[M,128] * B[N,128]^T (+bias[n]).  K fixed = 128.
// 128x128 block tile, 256 threads, 8x8 micro-tile, f32x2 packing over K
// (even/odd-k partial sums, reduced in epilogue). M must be a multiple of 128.
// =================================================================================
__global__ void __launch_bounds__(256, 1) gemm_tn128(
    const float* __restrict__ A, const float* __restrict__ B,
    const float* __restrict__ bias, float* __restrict__ C, int M, int N)
{
    extern __shared__ __align__(16) float smem[];
    float* As = smem;              // [128][128] row-major (m, k)
    float* Bs = smem + 128*128;    // [128][128] row-major (n, k)

    const int tid = threadIdx.x;
    const int m0 = blockIdx.y << 7;
    const int n0 = blockIdx.x << 7;

    {
        const float4* A4 = reinterpret_cast<const float4*>(A);
        const float4* B4 = reinterpret_cast<const float4*>(B);
        float4* As4 = reinterpret_cast<float4*>(As);
        float4* Bs4 = reinterpret_cast<float4*>(Bs);
#pragma unroll
        for (int i = tid; i < 128*32; i += 256) {
            int r = i >> 5, c = i & 31;
            As4[i] = A4[(m0 + r)*32 + c];
            int gr = n0 + r; gr = (gr < N) ? gr : (N - 1);   // clamp partial tile
            Bs4[i] = B4[gr*32 + c];
        }
    }
    __syncthreads();

    const int tx = tid & 15, ty = tid >> 4;
    unsigned long long acc[8][8];
#pragma unroll
    for (int i = 0; i < 8; i++)
#pragma unroll
        for (int j = 0; j < 8; j++) acc[i][j] = 0ull;

#pragma unroll 4
    for (int t = 0; t < 64; ++t) {
        unsigned long long a2[8], b2[8];
#pragma unroll
        for (int i = 0; i < 4; i++) {
            a2[i]   = *reinterpret_cast<const unsigned long long*>(&As[(ty*4+i)*128      + 2*t]);
            a2[4+i] = *reinterpret_cast<const unsigned long long*>(&As[(64+ty*4+i)*128   + 2*t]);
            b2[i]   = *reinterpret_cast<const unsigned long long*>(&Bs[(tx*4+i)*128      + 2*t]);
            b2[4+i] = *reinterpret_cast<const unsigned long long*>(&Bs[(64+tx*4+i)*128   + 2*t]);
        }
#pragma unroll
        for (int i = 0; i < 8; i++)
#pragma unroll
            for (int j = 0; j < 8; j++)
                FMA2(acc[i][j], a2[i], b2[j]);
    }

#pragma unroll
    for (int i = 0; i < 8; i++) {
        int row = m0 + ((i < 4) ? (ty*4 + i) : (64 + ty*4 + i - 4));
#pragma unroll
        for (int j = 0; j < 8; j++) {
            int col = n0 + ((j < 4) ? (tx*4 + j) : (64 + tx*4 + j - 4));
            if (col < N) {
                float2 p = *reinterpret_cast<float2*>(&acc[i][j]);
                float v = p.x + p.y;
                if (bias) v += bias[col];
                C[row * N + col] = v;
            }
        }
    }
}

// ---------------- small kernels ----------------

__global__ void transpose128_k(const float* __restrict__ G, float* __restrict__ GT) {
    int i = blockIdx.x * 256 + threadIdx.x;      // 16384 total
    int k = i >> 7, j = i & 127;
    GT[j*128 + k] = G[i];
}

__global__ void gather_x_k(const int* __restrict__ items, const float* __restrict__ emb,
                           float* __restrict__ x) {
    int n = blockIdx.x, t = threadIdx.x;
    x[n*H_ + t] = emb[items[n]*H_ + t];
}

__global__ void segsum_k(const float* __restrict__ m, const int* __restrict__ ei,
                         float* __restrict__ agg) {
    __shared__ float ms[NS_][H_];
    __shared__ float as[NS_][H_];
    int b = blockIdx.x, t = threadIdx.x;
#pragma unroll
    for (int j = 0; j < NS_; j++) { ms[j][t] = m[(b*NS_ + j)*H_ + t]; as[j][t] = 0.f; }
    __syncthreads();
    const int* src = ei + b*EPS_;
    const int* dst = ei + B_*EPS_ + b*EPS_;
#pragma unroll
    for (int e = 0; e < EPS_; e++) {
        int s = src[e] - b*NS_;
        int d = dst[e] - b*NS_;
        as[d][t] += ms[s][t];   // each thread owns column t -> race-free
    }
#pragma unroll
    for (int j = 0; j < NS_; j++) agg[(b*NS_ + j)*H_ + t] = as[j][t];
}

__global__ void gru_update_k(const float* __restrict__ gi, const float* __restrict__ gh,
                             float* __restrict__ x) {
    int i = blockIdx.x * 256 + threadIdx.x;      // < 8192*128
    int n = i >> 7, h = i & 127;
    const float* gin = gi + n*3*H_;
    const float* ghn = gh + n*3*H_;
    float ir = gin[h], iz = gin[H_ + h], in_ = gin[2*H_ + h];
    float hr = ghn[h], hz = ghn[H_ + h], hn  = ghn[2*H_ + h];
    float r = 1.f / (1.f + expf(-(ir + hr)));
    float z = 1.f / (1.f + expf(-(iz + hz)));
    float nn = tanhf(in_ + r*hn);
    x[i] = (1.f - z)*nn + z*x[i];
}

__global__ void build_hidden_k(const int* __restrict__ seq, const int* __restrict__ items,
                               const float* __restrict__ x, const float* __restrict__ emb,
                               float* __restrict__ hid) {
    int bl = blockIdx.x;          // b*L + l
    int b = bl / L_, t = threadIdx.x;
    int s = seq[bl];
    float v = 0.f;
    if (s != 0) {
        int j = -1;
#pragma unroll
        for (int q = 0; q < NS_; q++) if (j < 0 && items[b*NS_ + q] == s) j = q;
        v = (j >= 0) ? x[(b*NS_ + j)*H_ + t] : emb[s*H_ + t];
    }
    hid[bl*H_ + t] = v;
}

__device__ __forceinline__ float bsum128(float v, float* s4) {
#pragma unroll
    for (int o = 16; o > 0; o >>= 1) v += __shfl_xor_sync(0xffffffffu, v, o);
    int w = threadIdx.x >> 5;
    if ((threadIdx.x & 31) == 0) s4[w] = v;
    __syncthreads();
    v = s4[0] + s4[1] + s4[2] + s4[3];
    __syncthreads();
    return v;
}

__global__ void attention_k(const float* __restrict__ hid_g, const int* __restrict__ mask,
                            const float* __restrict__ W1, const float* __restrict__ b1,
                            const float* __restrict__ W2, const float* __restrict__ b2,
                            const float* __restrict__ w3, const float* __restrict__ Wt,
                            const float* __restrict__ bt, const float* __restrict__ gamma,
                            const float* __restrict__ beta, float* __restrict__ outA)
{
    __shared__ float hid[L_][H_];
    __shared__ float a_sh[H_];
    __shared__ float red[4];
    int b = blockIdx.x, t = threadIdx.x;
#pragma unroll
    for (int l = 0; l < L_; l++) hid[l][t] = hid_g[(b*L_ + l)*H_ + t];
    int len = 0;
#pragma unroll
    for (int l = 0; l < L_; l++) len += mask[b*L_ + l];
    __syncthreads();

    const float* ht = hid[len - 1];
    float q1 = b1[t];
#pragma unroll 8
    for (int k = 0; k < H_; k++) q1 += W1[t*H_ + k] * ht[k];
    float w3t = w3[t];

    float acc = 0.f;
    for (int l = 0; l < L_; l++) {
        float q2 = b2[t];
#pragma unroll 8
        for (int k = 0; k < H_; k++) q2 += W2[t*H_ + k] * hid[l][k];
        float v = (1.f / (1.f + expf(-(q1 + q2)))) * w3t;
        float alpha = bsum128(v, red);
        acc += alpha * hid[l][t] * (float)mask[b*L_ + l];
    }
    a_sh[t] = acc;
    __syncthreads();

    float o = bt[t];
#pragma unroll 8
    for (int k = 0; k < H_; k++) o += Wt[t*2*H_ + k] * a_sh[k];
#pragma unroll 8
    for (int k = 0; k < H_; k++) o += Wt[t*2*H_ + H_ + k] * ht[k];

    float mu = bsum128(o, red) * (1.f / H_);
    float d = o - mu;
    float var = bsum128(d*d, red) * (1.f / H_);
    outA[b*H_ + t] = d * rsqrtf(var + 1e-5f) * gamma[t] + beta[t];
}

// =================================================================================
extern "C" void kernel_launch(void* const* d_in, const int* in_sizes, int n_in,
                              void* d_out, int out_size)
{
    const int*   items    = (const int*)d_in[0];
    const int*   edge     = (const int*)d_in[1];
    const int*   sequence = (const int*)d_in[2];
    const int*   mask     = (const int*)d_in[3];
    const float* emb      = (const float*)d_in[4];
    const float* ggnn_w   = (const float*)d_in[5];
    const float* W_ih     = (const float*)d_in[6];
    const float* W_hh     = (const float*)d_in[7];
    const float* b_ih     = (const float*)d_in[8];
    const float* b_hh     = (const float*)d_in[9];
    const float* W1       = (const float*)d_in[10];
    const float* b1       = (const float*)d_in[11];
    const float* W2       = (const float*)d_in[12];
    const float* b2       = (const float*)d_in[13];
    const float* w3       = (const float*)d_in[14];
    const float* Wt       = (const float*)d_in[15];
    const float* bt       = (const float*)d_in[16];
    const float* gamma    = (const float*)d_in[17];
    const float* beta     = (const float*)d_in[18];
    float* out = (float*)d_out;

    float *px, *pm, *pagg, *pgt, *pgi, *pgh, *phid, *pa;
    cudaGetSymbolAddress((void**)&px,   g_x);
    cudaGetSymbolAddress((void**)&pm,   g_m);
    cudaGetSymbolAddress((void**)&pagg, g_agg);
    cudaGetSymbolAddress((void**)&pgt,  g_gt);
    cudaGetSymbolAddress((void**)&pgi,  g_gi);
    cudaGetSymbolAddress((void**)&pgh,  g_gh);
    cudaGetSymbolAddress((void**)&phid, g_hidden);
    cudaGetSymbolAddress((void**)&pa,   g_av);

    cudaFuncSetAttribute(gemm_tn128, cudaFuncAttributeMaxDynamicSharedMemorySize, 131072);

    // 1) G^T for x @ G
    transpose128_k<<<64, 256>>>(ggnn_w, pgt);
    // 2) x = embedding[items]
    gather_x_k<<<NN_, 128>>>(items, emb, px);
    // 3) m = x @ G
    gemm_tn128<<<dim3(1, NN_/128), 256, 131072>>>(px, pgt, nullptr, pm, NN_, H_);
    // 4) agg = segment_sum(m[src], dst)
    segsum_k<<<B_, 128>>>(pm, edge, pagg);
    // 5) gi = agg @ W_ih^T + b_ih ; gh = x @ W_hh^T + b_hh
    gemm_tn128<<<dim3(3, NN_/128), 256, 131072>>>(pagg, W_ih, b_ih, pgi, NN_, 3*H_);
    gemm_tn128<<<dim3(3, NN_/128), 256, 131072>>>(px,   W_hh, b_hh, pgh, NN_, 3*H_);
    // 6) GRU gate update (in-place on x)
    gru_update_k<<<NN_*H_/256, 256>>>(pgi, pgh, px);
    // 7) hidden[b,l] = matched node feature / embedding fallback / 0
    build_hidden_k<<<B_*L_, 128>>>(sequence, items, px, emb, phid);
    // 8) attention pooling + hybrid transform + layernorm -> a[512,128]
    attention_k<<<B_, 128>>>(phid, mask, W1, b1, W2, b2, w3, Wt, bt, gamma, beta, pa);
    // 9) scores = a @ embedding[1:]^T   [512, 99999]
    gemm_tn128<<<dim3((V_ - 1 + 127)/128, B_/128), 256, 131072>>>(pa, emb + H_, nullptr, out,
                                                                  B_, V_ - 1);
}

// round 5
// speedup vs baseline: 1.6699x; 1.6699x over previous
#include <cuda_runtime.h>
#include <math.h>

#define B_   512
#define L_   20
#define NS_  16
#define EPS_ 32
#define H_   128
#define V_   100000
#define NN_  (B_*NS_)   // 8192 nodes

#define SSTRIDE 130     // smem row stride in floats (520B): bank stride 2 -> conflict-free frags
#define SMEM_BYTES (2 * 128 * SSTRIDE * 4)

// ---------------- device scratch (no runtime allocation allowed) ----------------
__device__ float g_x[NN_*H_];
__device__ float g_m[NN_*H_];
__device__ float g_agg[NN_*H_];
__device__ float g_gt[H_*H_];
__device__ float g_gi[NN_*3*H_];
__device__ float g_gh[NN_*3*H_];
__device__ float g_hidden[B_*L_*H_];
__device__ float g_av[B_*H_];

// packed fp32x2 FMA (FFMA2 on sm_103a)
#define FMA2(acc, a, b) asm("fma.rn.f32x2 %0, %1, %2, %0;" : "+l"(acc) : "l"(a), "l"(b))

// =================================================================================
// C[M,N] = A[M,128] * B[N,128]^T (+bias[n]).  K fixed = 128.
// 128x128 block tile, 256 threads, 8x8 micro-tile (interleaved: rows ty+16i,
// cols tx+16j), f32x2 packing over K (even/odd-k partials, reduced in epilogue).
// Smem rows padded to 130 floats -> conflict-free fragment loads.
// M must be a multiple of 128.
// =================================================================================
__global__ void __launch_bounds__(256, 1) gemm_tn128(
    const float* __restrict__ A, const float* __restrict__ B,
    const float* __restrict__ bias, float* __restrict__ C, int M, int N)
{
    extern __shared__ __align__(16) float smem[];
    float* As = smem;                    // [128][SSTRIDE] (m, k)
    float* Bs = smem + 128*SSTRIDE;      // [128][SSTRIDE] (n, k)

    const int tid = threadIdx.x;
    const int m0 = blockIdx.y << 7;
    const int n0 = blockIdx.x << 7;

    {
        const float4* A4 = reinterpret_cast<const float4*>(A);
        const float4* B4 = reinterpret_cast<const float4*>(B);
#pragma unroll
        for (int i = tid; i < 128*32; i += 256) {
            int r = i >> 5, c = i & 31;
            float4 va = A4[(m0 + r)*32 + c];
            float2* pa = reinterpret_cast<float2*>(&As[r*SSTRIDE + 4*c]);
            pa[0] = make_float2(va.x, va.y);
            pa[1] = make_float2(va.z, va.w);
            int gr = n0 + r; gr = (gr < N) ? gr : (N - 1);   // clamp partial tile
            float4 vb = B4[gr*32 + c];
            float2* pb = reinterpret_cast<float2*>(&Bs[r*SSTRIDE + 4*c]);
            pb[0] = make_float2(vb.x, vb.y);
            pb[1] = make_float2(vb.z, vb.w);
        }
    }
    __syncthreads();

    const int tx = tid & 15, ty = tid >> 4;
    unsigned long long acc[8][8];
#pragma unroll
    for (int i = 0; i < 8; i++)
#pragma unroll
        for (int j = 0; j < 8; j++) acc[i][j] = 0ull;

#pragma unroll 8
    for (int t = 0; t < 64; ++t) {
        unsigned long long a2[8], b2[8];
#pragma unroll
        for (int i = 0; i < 8; i++) {
            a2[i] = *reinterpret_cast<const unsigned long long*>(&As[(16*i + ty)*SSTRIDE + 2*t]);
            b2[i] = *reinterpret_cast<const unsigned long long*>(&Bs[(16*i + tx)*SSTRIDE + 2*t]);
        }
#pragma unroll
        for (int i = 0; i < 8; i++)
#pragma unroll
            for (int j = 0; j < 8; j++)
                FMA2(acc[i][j], a2[i], b2[j]);
    }

#pragma unroll
    for (int i = 0; i < 8; i++) {
        int row = m0 + ty + 16*i;
#pragma unroll
        for (int j = 0; j < 8; j++) {
            int col = n0 + tx + 16*j;
            if (col < N) {
                float2 p = *reinterpret_cast<float2*>(&acc[i][j]);
                float v = p.x + p.y;
                if (bias) v += bias[col];
                C[row * N + col] = v;
            }
        }
    }
}

// ---------------- small kernels ----------------

__global__ void transpose128_k(const float* __restrict__ G, float* __restrict__ GT) {
    int i = blockIdx.x * 256 + threadIdx.x;      // 16384 total
    int k = i >> 7, j = i & 127;
    GT[j*128 + k] = G[i];
}

__global__ void gather_x_k(const int* __restrict__ items, const float* __restrict__ emb,
                           float* __restrict__ x) {
    int n = blockIdx.x, t = threadIdx.x;
    x[n*H_ + t] = emb[items[n]*H_ + t];
}

__global__ void segsum_k(const float* __restrict__ m, const int* __restrict__ ei,
                         float* __restrict__ agg) {
    __shared__ float ms[NS_][H_];
    __shared__ float as[NS_][H_];
    int b = blockIdx.x, t = threadIdx.x;
#pragma unroll
    for (int j = 0; j < NS_; j++) { ms[j][t] = m[(b*NS_ + j)*H_ + t]; as[j][t] = 0.f; }
    __syncthreads();
    const int* src = ei + b*EPS_;
    const int* dst = ei + B_*EPS_ + b*EPS_;
#pragma unroll
    for (int e = 0; e < EPS_; e++) {
        int s = src[e] - b*NS_;
        int d = dst[e] - b*NS_;
        as[d][t] += ms[s][t];   // each thread owns column t -> race-free
    }
#pragma unroll
    for (int j = 0; j < NS_; j++) agg[(b*NS_ + j)*H_ + t] = as[j][t];
}

__global__ void gru_update_k(const float* __restrict__ gi, const float* __restrict__ gh,
                             float* __restrict__ x) {
    int i = blockIdx.x * 256 + threadIdx.x;      // < 8192*128
    int n = i >> 7, h = i & 127;
    const float* gin = gi + n*3*H_;
    const float* ghn = gh + n*3*H_;
    float ir = gin[h], iz = gin[H_ + h], in_ = gin[2*H_ + h];
    float hr = ghn[h], hz = ghn[H_ + h], hn  = ghn[2*H_ + h];
    float r = 1.f / (1.f + expf(-(ir + hr)));
    float z = 1.f / (1.f + expf(-(iz + hz)));
    float nn = tanhf(in_ + r*hn);
    x[i] = (1.f - z)*nn + z*x[i];
}

__global__ void build_hidden_k(const int* __restrict__ seq, const int* __restrict__ items,
                               const float* __restrict__ x, const float* __restrict__ emb,
                               float* __restrict__ hid) {
    int bl = blockIdx.x;          // b*L + l
    int b = bl / L_, t = threadIdx.x;
    int s = seq[bl];
    float v = 0.f;
    if (s != 0) {
        int j = -1;
#pragma unroll
        for (int q = 0; q < NS_; q++) if (j < 0 && items[b*NS_ + q] == s) j = q;
        v = (j >= 0) ? x[(b*NS_ + j)*H_ + t] : emb[s*H_ + t];
    }
    hid[bl*H_ + t] = v;
}

__device__ __forceinline__ float bsum128(float v, float* s4) {
#pragma unroll
    for (int o = 16; o > 0; o >>= 1) v += __shfl_xor_sync(0xffffffffu, v, o);
    int w = threadIdx.x >> 5;
    if ((threadIdx.x & 31) == 0) s4[w] = v;
    __syncthreads();
    v = s4[0] + s4[1] + s4[2] + s4[3];
    __syncthreads();
    return v;
}

__global__ void attention_k(const float* __restrict__ hid_g, const int* __restrict__ mask,
                            const float* __restrict__ W1, const float* __restrict__ b1,
                            const float* __restrict__ W2, const float* __restrict__ b2,
                            const float* __restrict__ w3, const float* __restrict__ Wt,
                            const float* __restrict__ bt, const float* __restrict__ gamma,
                            const float* __restrict__ beta, float* __restrict__ outA)
{
    __shared__ float hid[L_][H_];
    __shared__ float a_sh[H_];
    __shared__ float red[4];
    int b = blockIdx.x, t = threadIdx.x;
#pragma unroll
    for (int l = 0; l < L_; l++) hid[l][t] = hid_g[(b*L_ + l)*H_ + t];
    int len = 0;
#pragma unroll
    for (int l = 0; l < L_; l++) len += mask[b*L_ + l];
    __syncthreads();

    const float* ht = hid[len - 1];
    float q1 = b1[t];
#pragma unroll 8
    for (int k = 0; k < H_; k++) q1 += W1[t*H_ + k] * ht[k];
    float w3t = w3[t];

    float acc = 0.f;
    for (int l = 0; l < L_; l++) {
        float q2 = b2[t];
#pragma unroll 8
        for (int k = 0; k < H_; k++) q2 += W2[t*H_ + k] * hid[l][k];
        float v = (1.f / (1.f + expf(-(q1 + q2)))) * w3t;
        float alpha = bsum128(v, red);
        acc += alpha * hid[l][t] * (float)mask[b*L_ + l];
    }
    a_sh[t] = acc;
    __syncthreads();

    float o = bt[t];
#pragma unroll 8
    for (int k = 0; k < H_; k++) o += Wt[t*2*H_ + k] * a_sh[k];
#pragma unroll 8
    for (int k = 0; k < H_; k++) o += Wt[t*2*H_ + H_ + k] * ht[k];

    float mu = bsum128(o, red) * (1.f / H_);
    float d = o - mu;
    float var = bsum128(d*d, red) * (1.f / H_);
    outA[b*H_ + t] = d * rsqrtf(var + 1e-5f) * gamma[t] + beta[t];
}

// =================================================================================
extern "C" void kernel_launch(void* const* d_in, const int* in_sizes, int n_in,
                              void* d_out, int out_size)
{
    const int*   items    = (const int*)d_in[0];
    const int*   edge     = (const int*)d_in[1];
    const int*   sequence = (const int*)d_in[2];
    const int*   mask     = (const int*)d_in[3];
    const float* emb      = (const float*)d_in[4];
    const float* ggnn_w   = (const float*)d_in[5];
    const float* W_ih     = (const float*)d_in[6];
    const float* W_hh     = (const float*)d_in[7];
    const float* b_ih     = (const float*)d_in[8];
    const float* b_hh     = (const float*)d_in[9];
    const float* W1       = (const float*)d_in[10];
    const float* b1       = (const float*)d_in[11];
    const float* W2       = (const float*)d_in[12];
    const float* b2       = (const float*)d_in[13];
    const float* w3       = (const float*)d_in[14];
    const float* Wt       = (const float*)d_in[15];
    const float* bt       = (const float*)d_in[16];
    const float* gamma    = (const float*)d_in[17];
    const float* beta     = (const float*)d_in[18];
    float* out = (float*)d_out;

    float *px, *pm, *pagg, *pgt, *pgi, *pgh, *phid, *pa;
    cudaGetSymbolAddress((void**)&px,   g_x);
    cudaGetSymbolAddress((void**)&pm,   g_m);
    cudaGetSymbolAddress((void**)&pagg, g_agg);
    cudaGetSymbolAddress((void**)&pgt,  g_gt);
    cudaGetSymbolAddress((void**)&pgi,  g_gi);
    cudaGetSymbolAddress((void**)&pgh,  g_gh);
    cudaGetSymbolAddress((void**)&phid, g_hidden);
    cudaGetSymbolAddress((void**)&pa,   g_av);

    cudaFuncSetAttribute(gemm_tn128, cudaFuncAttributeMaxDynamicSharedMemorySize, SMEM_BYTES);

    // 1) G^T for x @ G
    transpose128_k<<<64, 256>>>(ggnn_w, pgt);
    // 2) x = embedding[items]
    gather_x_k<<<NN_, 128>>>(items, emb, px);
    // 3) m = x @ G
    gemm_tn128<<<dim3(1, NN_/128), 256, SMEM_BYTES>>>(px, pgt, nullptr, pm, NN_, H_);
    // 4) agg = segment_sum(m[src], dst)
    segsum_k<<<B_, 128>>>(pm, edge, pagg);
    // 5) gi = agg @ W_ih^T + b_ih ; gh = x @ W_hh^T + b_hh
    gemm_tn128<<<dim3(3, NN_/128), 256, SMEM_BYTES>>>(pagg, W_ih, b_ih, pgi, NN_, 3*H_);
    gemm_tn128<<<dim3(3, NN_/128), 256, SMEM_BYTES>>>(px,   W_hh, b_hh, pgh, NN_, 3*H_);
    // 6) GRU gate update (in-place on x)
    gru_update_k<<<NN_*H_/256, 256>>>(pgi, pgh, px);
    // 7) hidden[b,l] = matched node feature / embedding fallback / 0
    build_hidden_k<<<B_*L_, 128>>>(sequence, items, px, emb, phid);
    // 8) attention pooling + hybrid transform + layernorm -> a[512,128]
    attention_k<<<B_, 128>>>(phid, mask, W1, b1, W2, b2, w3, Wt, bt, gamma, beta, pa);
    // 9) scores = a @ embedding[1:]^T   [512, 99999]
    gemm_tn128<<<dim3((V_ - 1 + 127)/128, B_/128), 256, SMEM_BYTES>>>(pa, emb + H_, nullptr, out,
                                                                      B_, V_ - 1);
}